// round 13
// baseline (speedup 1.0000x reference)
#include <cuda_runtime.h>
#include <cstddef>
#include <cstdint>

#define NP 4
#define NS 4
#define NC 64
#define NF 64
#define NB 64
// PS = 16, PSC = 1024, per-psc KQ block = F*C*F = 262144 floats

__device__ float g_weights[NP * NS * NC * NC];           // softmax(scores), 256 KB
__device__ float g_V[NB * NP * NS * NC * NF];            // V = X @ Wv^T, 16 MB

// packed fp32x2 FMA: {d.lo,d.hi} += {a.lo*b.lo, a.hi*b.hi} — exact fp32, 2x rate
__device__ __forceinline__ void ffma2(unsigned long long& acc,
                                      unsigned long long a,
                                      unsigned long long b) {
    asm("fma.rn.f32x2 %0, %1, %2, %0;" : "+l"(acc) : "l"(a), "l"(b));
}
// pack one fp32 into both lanes of a 64-bit pair (ALU pipe, 1 instr)
__device__ __forceinline__ unsigned long long dup2(float w) {
    unsigned long long r;
    asm("mov.b64 %0, {%1, %1};" : "=l"(r) : "f"(w));
    return r;
}

// ---------------------------------------------------------------------------
// Kernel 1 (unchanged, 89.5% of HBM spec): 2048 blocks x 1024 threads.
// EVEN blocks (psc = bid>>1): KQ reduction + fused softmax.
// ODD  blocks (bp  = bid>>1): V[bp] = X[bp] @ Wv^T in the idle issue slots.
// ---------------------------------------------------------------------------
__global__ void __launch_bounds__(1024, 2)
reduce_softmax_v_kernel(const float* __restrict__ kq,
                        const float* __restrict__ x,
                        const float* __restrict__ wv) {
    __shared__ float sh[NC * (NF + 1) + NC * (NF + 4)];  // 34 KB union

    const int bid = blockIdx.x;
    const int t   = threadIdx.x;

    if ((bid & 1) == 0) {
        // ---- role A: KQ reduction + softmax ----
        const int psc = bid >> 1;
        const int d   = t >> 4;
        const int j   = t & 15;

        const float4* base =
            reinterpret_cast<const float4*>(kq + (size_t)psc * (NF * NC * NF))
            + (d * (NF / 4) + j);

        float4 acc = make_float4(0.f, 0.f, 0.f, 0.f);
#pragma unroll 4
        for (int f = 0; f < NF; ++f) {
            float4 v = __ldcs(base + f * (NC * NF / 4));
            acc.x += v.x; acc.y += v.y; acc.z += v.z; acc.w += v.w;
        }
        float s = (acc.x + acc.y) + (acc.z + acc.w);

        s += __shfl_xor_sync(0xffffffffu, s, 8);
        s += __shfl_xor_sync(0xffffffffu, s, 4);
        s += __shfl_xor_sync(0xffffffffu, s, 2);
        s += __shfl_xor_sync(0xffffffffu, s, 1);

        if (j == 0) sh[d] = s;
        __syncthreads();

        if (t < 32) {
            const float a = sh[t];
            const float b = sh[t + 32];
            float m = fmaxf(a, b);
#pragma unroll
            for (int off = 16; off > 0; off >>= 1)
                m = fmaxf(m, __shfl_xor_sync(0xffffffffu, m, off));
            const float ea = __expf(a - m);
            const float eb = __expf(b - m);
            float ssum = ea + eb;
#pragma unroll
            for (int off = 16; off > 0; off >>= 1)
                ssum += __shfl_xor_sync(0xffffffffu, ssum, off);
            const float inv = 1.0f / ssum;
            g_weights[psc * NC + t]      = ea * inv;
            g_weights[psc * NC + t + 32] = eb * inv;
        }
    } else {
        // ---- role B: V = X @ Wv^T for one (b,ps), float4-vectorized ----
        const int bp = bid >> 1;                    // = b*16 + ps
        float* bufX  = sh;                          // [64][65] : X[c][k]
        float* bufWT = sh + NC * (NF + 1);          // [64][68] : Wv^T[k][f]

        const float* xsrc = x + (size_t)bp * (NC * NF);
#pragma unroll
        for (int r = 0; r < 4; ++r) {
            const int idx = t + r * 1024;
            const int hi  = idx >> 6, lo = idx & 63;
            bufX[hi * (NF + 1) + lo]  = xsrc[idx];
            bufWT[lo * (NF + 4) + hi] = wv[idx];    // wv[f][k] -> bufWT[k][f]
        }
        __syncthreads();

        const int c  = t >> 4;
        const int fq = t & 15;
        float4 acc = make_float4(0.f, 0.f, 0.f, 0.f);
#pragma unroll 8
        for (int k = 0; k < NF; ++k) {
            const float  xk = bufX[c * (NF + 1) + k];
            const float4 w4 = *reinterpret_cast<const float4*>(
                                  &bufWT[k * (NF + 4) + 4 * fq]);
            acc.x += xk * w4.x; acc.y += xk * w4.y;
            acc.z += xk * w4.z; acc.w += xk * w4.w;
        }

        float4* vdst = reinterpret_cast<float4*>(g_V + (size_t)bp * (NC * NF));
        vdst[c * (NF / 4) + fq] = acc;
    }
}

// ---------------------------------------------------------------------------
// Kernel 2: out[b,ps][c][f] = sum_d w[ps][c][d] * V[b,ps][d][f]
// 1024 blocks x 128 threads, 8c x 4f register tile (R9 pattern: w from smem
// via broadcast LDS.128, V conflict-free LDS.128, FFMA2 + register dup2).
// R11 deltas vs R9: bufW stride 68 -> 64 (w reads are BROADCASTS; padding
// bought nothing) -> smem 34->32 KB; launch_bounds(128,7) caps regs at 73
// -> 7 blocks/SM = 43.8% occ (was 24.3%); unroll 2 trims live V registers.
// ---------------------------------------------------------------------------
__global__ void __launch_bounds__(128, 7)
attn_out_kernel(float* __restrict__ out) {
    __shared__ float bufV[NC * NF];         // V[d][f], flat
    __shared__ float bufW[NC * NF];         // w[c][d], flat

    const int blk = blockIdx.x;
    const int b   = blk >> 4;
    const int ps  = blk & 15;
    const int t   = threadIdx.x;
    const int tcg = t >> 4;                 // 0..7
    const int tf  = t & 15;                 // 0..15

    const float4* vsrc = reinterpret_cast<const float4*>(g_V + (size_t)blk * (NC * NF));
    const float4* wsrc = reinterpret_cast<const float4*>(g_weights + (size_t)ps * (NC * NC));
    float4* bv4 = reinterpret_cast<float4*>(bufV);
    float4* bw4 = reinterpret_cast<float4*>(bufW);
#pragma unroll
    for (int r = 0; r < 8; ++r) {
        const int i4 = t + r * 128;                  // 0..1023 float4s
        bv4[i4] = vsrc[i4];
        bw4[i4] = wsrc[i4];
    }
    __syncthreads();

    unsigned long long o01[8], o23[8];   // per c-row: {f,f+1} and {f+2,f+3}
#pragma unroll
    for (int i = 0; i < 8; ++i) { o01[i] = 0ull; o23[i] = 0ull; }

    const int frow = 4 * tf;

#pragma unroll 2
    for (int d4 = 0; d4 < NC / 4; ++d4) {
        // V rows for d = 4*d4 .. 4*d4+3, f-slice [frow, frow+4) as u64 pairs
        const ulonglong2 v0 = *reinterpret_cast<const ulonglong2*>(&bufV[(4 * d4 + 0) * NF + frow]);
        const ulonglong2 v1 = *reinterpret_cast<const ulonglong2*>(&bufV[(4 * d4 + 1) * NF + frow]);
        const ulonglong2 v2 = *reinterpret_cast<const ulonglong2*>(&bufV[(4 * d4 + 2) * NF + frow]);
        const ulonglong2 v3 = *reinterpret_cast<const ulonglong2*>(&bufV[(4 * d4 + 3) * NF + frow]);

#pragma unroll
        for (int i = 0; i < 8; ++i) {
            // broadcast LDS.128: 2 distinct c addresses per warp
            const float4 w4 = *reinterpret_cast<const float4*>(
                                  &bufW[(tcg + 8 * i) * NF + 4 * d4]);
            const unsigned long long wx = dup2(w4.x);
            const unsigned long long wy = dup2(w4.y);
            const unsigned long long wz = dup2(w4.z);
            const unsigned long long ww = dup2(w4.w);
            ffma2(o01[i], wx, v0.x);  ffma2(o23[i], wx, v0.y);
            ffma2(o01[i], wy, v1.x);  ffma2(o23[i], wy, v1.y);
            ffma2(o01[i], wz, v2.x);  ffma2(o23[i], wz, v2.y);
            ffma2(o01[i], ww, v3.x);  ffma2(o23[i], ww, v3.y);
        }
    }

    // out layout: (C, B, P*S*F); out[c, b, ps*F + f], f-slice [frow, frow+4)
#pragma unroll
    for (int i = 0; i < 8; ++i) {
        const int c = tcg + 8 * i;
        float* orow = out + ((size_t)c * NB + b) * (NP * NS * NF) + (size_t)ps * NF;
        float4 o;
        o.x = __uint_as_float((unsigned)(o01[i] & 0xffffffffull));
        o.y = __uint_as_float((unsigned)(o01[i] >> 32));
        o.z = __uint_as_float((unsigned)(o23[i] & 0xffffffffull));
        o.w = __uint_as_float((unsigned)(o23[i] >> 32));
        *reinterpret_cast<float4*>(&orow[frow]) = o;
    }
}

// ---------------------------------------------------------------------------
extern "C" void kernel_launch(void* const* d_in, const int* in_sizes, int n_in,
                              void* d_out, int out_size) {
    const float* X  = (const float*)d_in[0];  // (B, P*S*C*F)
    const float* KQ = (const float*)d_in[1];  // (P,S,C,F,C,F) — 1 GB
    const float* Wv = (const float*)d_in[2];  // (F, F)
    float* out = (float*)d_out;               // (C, B, P*S*F)

    reduce_softmax_v_kernel<<<2048, 1024>>>(KQ, X, Wv);
    attn_out_kernel<<<NB * NP * NS, 128>>>(out);
}

// round 15
// speedup vs baseline: 1.1142x; 1.1142x over previous
#include <cuda_runtime.h>
#include <cstddef>
#include <cstdint>

#define NP 4
#define NS 4
#define NC 64
#define NF 64
#define NB 64
// PS = 16, PSC = 1024, per-psc KQ block = F*C*F = 262144 floats

__device__ float g_weights[NP * NS * NC * NC];           // softmax(scores), 256 KB
__device__ float g_V[NB * NP * NS * NC * NF];            // V = X @ Wv^T, 16 MB

// packed fp32x2 FMA: {d.lo,d.hi} += {a.lo*b.lo, a.hi*b.hi} — exact fp32, 2x rate
__device__ __forceinline__ void ffma2(unsigned long long& acc,
                                      unsigned long long a,
                                      unsigned long long b) {
    asm("fma.rn.f32x2 %0, %1, %2, %0;" : "+l"(acc) : "l"(a), "l"(b));
}
// pack one fp32 into both lanes of a 64-bit pair (ALU pipe, 1 instr)
__device__ __forceinline__ unsigned long long dup2(float w) {
    unsigned long long r;
    asm("mov.b64 %0, {%1, %1};" : "=l"(r) : "f"(w));
    return r;
}

// ---------------------------------------------------------------------------
// Kernel 1 (unchanged, 89.5% of HBM spec): 2048 blocks x 1024 threads.
// EVEN blocks (psc = bid>>1): KQ reduction + fused softmax.
// ODD  blocks (bp  = bid>>1): V[bp] = X[bp] @ Wv^T in the idle issue slots.
// ---------------------------------------------------------------------------
__global__ void __launch_bounds__(1024, 2)
reduce_softmax_v_kernel(const float* __restrict__ kq,
                        const float* __restrict__ x,
                        const float* __restrict__ wv) {
    __shared__ float sh[NC * (NF + 1) + NC * (NF + 4)];  // 34 KB union

    const int bid = blockIdx.x;
    const int t   = threadIdx.x;

    if ((bid & 1) == 0) {
        // ---- role A: KQ reduction + softmax ----
        const int psc = bid >> 1;
        const int d   = t >> 4;
        const int j   = t & 15;

        const float4* base =
            reinterpret_cast<const float4*>(kq + (size_t)psc * (NF * NC * NF))
            + (d * (NF / 4) + j);

        float4 acc = make_float4(0.f, 0.f, 0.f, 0.f);
#pragma unroll 4
        for (int f = 0; f < NF; ++f) {
            float4 v = __ldcs(base + f * (NC * NF / 4));
            acc.x += v.x; acc.y += v.y; acc.z += v.z; acc.w += v.w;
        }
        float s = (acc.x + acc.y) + (acc.z + acc.w);

        s += __shfl_xor_sync(0xffffffffu, s, 8);
        s += __shfl_xor_sync(0xffffffffu, s, 4);
        s += __shfl_xor_sync(0xffffffffu, s, 2);
        s += __shfl_xor_sync(0xffffffffu, s, 1);

        if (j == 0) sh[d] = s;
        __syncthreads();

        if (t < 32) {
            const float a = sh[t];
            const float b = sh[t + 32];
            float m = fmaxf(a, b);
#pragma unroll
            for (int off = 16; off > 0; off >>= 1)
                m = fmaxf(m, __shfl_xor_sync(0xffffffffu, m, off));
            const float ea = __expf(a - m);
            const float eb = __expf(b - m);
            float ssum = ea + eb;
#pragma unroll
            for (int off = 16; off > 0; off >>= 1)
                ssum += __shfl_xor_sync(0xffffffffu, ssum, off);
            const float inv = 1.0f / ssum;
            g_weights[psc * NC + t]      = ea * inv;
            g_weights[psc * NC + t + 32] = eb * inv;
        }
    } else {
        // ---- role B: V = X @ Wv^T for one (b,ps), float4-vectorized ----
        const int bp = bid >> 1;                    // = b*16 + ps
        float* bufX  = sh;                          // [64][65] : X[c][k]
        float* bufWT = sh + NC * (NF + 1);          // [64][68] : Wv^T[k][f]

        const float* xsrc = x + (size_t)bp * (NC * NF);
#pragma unroll
        for (int r = 0; r < 4; ++r) {
            const int idx = t + r * 1024;
            const int hi  = idx >> 6, lo = idx & 63;
            bufX[hi * (NF + 1) + lo]  = xsrc[idx];
            bufWT[lo * (NF + 4) + hi] = wv[idx];    // wv[f][k] -> bufWT[k][f]
        }
        __syncthreads();

        const int c  = t >> 4;
        const int fq = t & 15;
        float4 acc = make_float4(0.f, 0.f, 0.f, 0.f);
#pragma unroll 8
        for (int k = 0; k < NF; ++k) {
            const float  xk = bufX[c * (NF + 1) + k];
            const float4 w4 = *reinterpret_cast<const float4*>(
                                  &bufWT[k * (NF + 4) + 4 * fq]);
            acc.x += xk * w4.x; acc.y += xk * w4.y;
            acc.z += xk * w4.z; acc.w += xk * w4.w;
        }

        float4* vdst = reinterpret_cast<float4*>(g_V + (size_t)bp * (NC * NF));
        vdst[c * (NF / 4) + fq] = acc;
    }
}

// ---------------------------------------------------------------------------
// Kernel 2: out[b,ps][c][f] = sum_d w[ps][c][d] * V[b,ps][d][f]
// R13: HALF-TILE split. 2048 blocks x 128 threads; block (bp, half) handles
// c-rows [32*half, 32*half+32) x all 64 f.  Per-thread 4c x 4f tile (the
// proven R5 inner loop: broadcast w LDS.128, conflict-free V LDS.128, dup2
// + FFMA2).  smem = full V (16KB) + HALF w (8KB) = 24KB; regs ~55 natural
// (NO launch_bounds cap — caps spill, proven twice) -> ~9 blocks/SM = 56%
// occ (was 24%), 1.5 waves.
// ---------------------------------------------------------------------------
__global__ void __launch_bounds__(128)
attn_out_kernel(float* __restrict__ out) {
    __shared__ float bufV[NC * NF];               // V[d][f], 16 KB
    __shared__ float bufW[32 * (NF + 4)];         // w[c][d] half, stride 68

    const int blk  = blockIdx.x;
    const int bp   = blk >> 1;                    // b*16 + ps
    const int half = blk & 1;
    const int b    = bp >> 4;
    const int ps   = bp & 15;
    const int t    = threadIdx.x;
    const int tc   = t >> 4;                      // 0..7
    const int tf   = t & 15;                      // 0..15

    const float4* vsrc = reinterpret_cast<const float4*>(g_V + (size_t)bp * (NC * NF));
    const float4* wsrc = reinterpret_cast<const float4*>(
                             g_weights + (size_t)ps * (NC * NC) + half * 32 * NC);
    float4* bv4 = reinterpret_cast<float4*>(bufV);
#pragma unroll
    for (int r = 0; r < 8; ++r) {
        const int i4 = t + r * 128;               // 0..1023 float4s: full V
        bv4[i4] = vsrc[i4];
    }
#pragma unroll
    for (int r = 0; r < 4; ++r) {
        const int i4 = t + r * 128;               // 0..511 float4s: half w
        reinterpret_cast<float4*>(&bufW[(i4 >> 4) * (NF + 4)])[i4 & 15] = wsrc[i4];
    }
    __syncthreads();

    unsigned long long o01[4], o23[4];            // per c-row packed pairs
#pragma unroll
    for (int i = 0; i < 4; ++i) { o01[i] = 0ull; o23[i] = 0ull; }

    const int frow = 4 * tf;

#pragma unroll 4
    for (int d4 = 0; d4 < NC / 4; ++d4) {
        const ulonglong2 v0 = *reinterpret_cast<const ulonglong2*>(&bufV[(4 * d4 + 0) * NF + frow]);
        const ulonglong2 v1 = *reinterpret_cast<const ulonglong2*>(&bufV[(4 * d4 + 1) * NF + frow]);
        const ulonglong2 v2 = *reinterpret_cast<const ulonglong2*>(&bufV[(4 * d4 + 2) * NF + frow]);
        const ulonglong2 v3 = *reinterpret_cast<const ulonglong2*>(&bufV[(4 * d4 + 3) * NF + frow]);

#pragma unroll
        for (int i = 0; i < 4; ++i) {
            // broadcast LDS.128: 2 distinct local c addresses per warp
            const float4 w4 = *reinterpret_cast<const float4*>(
                                  &bufW[(tc + 8 * i) * (NF + 4) + 4 * d4]);
            const unsigned long long wx = dup2(w4.x);
            const unsigned long long wy = dup2(w4.y);
            const unsigned long long wz = dup2(w4.z);
            const unsigned long long ww = dup2(w4.w);
            ffma2(o01[i], wx, v0.x);  ffma2(o23[i], wx, v0.y);
            ffma2(o01[i], wy, v1.x);  ffma2(o23[i], wy, v1.y);
            ffma2(o01[i], wz, v2.x);  ffma2(o23[i], wz, v2.y);
            ffma2(o01[i], ww, v3.x);  ffma2(o23[i], ww, v3.y);
        }
    }

    // out layout: (C, B, P*S*F); out[c, b, ps*F + f], f-slice [frow, frow+4)
#pragma unroll
    for (int i = 0; i < 4; ++i) {
        const int c = half * 32 + tc + 8 * i;
        float* orow = out + ((size_t)c * NB + b) * (NP * NS * NF) + (size_t)ps * NF;
        float4 o;
        o.x = __uint_as_float((unsigned)(o01[i] & 0xffffffffull));
        o.y = __uint_as_float((unsigned)(o01[i] >> 32));
        o.z = __uint_as_float((unsigned)(o23[i] & 0xffffffffull));
        o.w = __uint_as_float((unsigned)(o23[i] >> 32));
        *reinterpret_cast<float4*>(&orow[frow]) = o;
    }
}

// ---------------------------------------------------------------------------
extern "C" void kernel_launch(void* const* d_in, const int* in_sizes, int n_in,
                              void* d_out, int out_size) {
    const float* X  = (const float*)d_in[0];  // (B, P*S*C*F)
    const float* KQ = (const float*)d_in[1];  // (P,S,C,F,C,F) — 1 GB
    const float* Wv = (const float*)d_in[2];  // (F, F)
    float* out = (float*)d_out;               // (C, B, P*S*F)

    reduce_softmax_v_kernel<<<2048, 1024>>>(KQ, X, Wv);
    attn_out_kernel<<<2 * NB * NP * NS, 128>>>(out);
}